// round 1
// baseline (speedup 1.0000x reference)
#include <cuda_runtime.h>

#define NMAX   1024
#define DDIM   128
#define MARGIN 1.9f

// Scratch (no allocation allowed): dist matrix + per-anchor partials + normalized labels
__device__ float g_dist[NMAX * NMAX];
__device__ float g_psum[NMAX];
__device__ int   g_pcnt[NMAX];
__device__ int   g_pvalid[NMAX];
__device__ int   g_lab[NMAX];

// ---------------------------------------------------------------------------
// Normalize labels to int32. Handles both int64 (low/high word pairs, LE) and
// int32 layouts: if the input is int64, the int32 view's odd entries (high
// words) are all zero for values 0..9; for genuine int32 random labels the
// probability all 320 odd entries are zero is ~1e-320.
// ---------------------------------------------------------------------------
__global__ void normalize_labels_kernel(const int* __restrict__ lab32, int n) {
    __shared__ int odd_nonzero;
    if (threadIdx.x == 0) odd_nonzero = 0;
    __syncthreads();
    for (int idx = threadIdx.x; idx < n / 2; idx += blockDim.x) {
        if (lab32[2 * idx + 1] != 0) atomicExch(&odd_nonzero, 1);
    }
    __syncthreads();
    bool is64 = (odd_nonzero == 0);
    for (int i = threadIdx.x; i < n; i += blockDim.x) {
        g_lab[i] = is64 ? lab32[2 * i] : lab32[i];
    }
}

// ---------------------------------------------------------------------------
// Pairwise Euclidean distance: dist[i][j] = sqrt(sum_k (e[i][k]-e[j][k])^2)
// 32x32 tile per block, 256 threads, B tile stored k-major (conflict-free).
// ---------------------------------------------------------------------------
__global__ void dist_kernel(const float* __restrict__ e, int n) {
    __shared__ float As[32][DDIM];      // row-major: As[i][k], broadcast reads
    __shared__ float Bs[DDIM][32];      // k-major:   Bs[k][j], conflict-free reads

    const int bi = blockIdx.y * 32;
    const int bj = blockIdx.x * 32;
    const int tid = threadIdx.x;        // 256 threads
    const float4* e4 = (const float4*)e; // DDIM/4 = 32 float4 per row

    // Load A tile: 32 rows x 32 float4 = 1024 float4, 4 per thread, coalesced.
    #pragma unroll
    for (int r = 0; r < 4; r++) {
        int lin = tid + r * 256;        // 0..1023
        int row = lin >> 5;             // 0..31
        int c4  = lin & 31;             // 0..31
        float4 v = e4[(size_t)(bi + row) * 32 + c4];
        *(float4*)&As[row][c4 * 4] = v;
    }
    // Load B tile transposed: lane -> j so shared stores are conflict-free.
    #pragma unroll
    for (int r = 0; r < 4; r++) {
        int lin = tid + r * 256;
        int j   = lin & 31;             // lane-varying -> distinct banks
        int c4  = lin >> 5;
        float4 v = e4[(size_t)(bj + j) * 32 + c4];
        Bs[c4 * 4 + 0][j] = v.x;
        Bs[c4 * 4 + 1][j] = v.y;
        Bs[c4 * 4 + 2][j] = v.z;
        Bs[c4 * 4 + 3][j] = v.w;
    }
    __syncthreads();

    const int tx = tid & 31;            // j within tile
    const int ty = tid >> 5;            // 0..7, i stride 8
    float acc0 = 0.f, acc1 = 0.f, acc2 = 0.f, acc3 = 0.f;
    #pragma unroll 4
    for (int k = 0; k < DDIM; k++) {
        float b = Bs[k][tx];
        float d0 = As[ty +  0][k] - b;
        float d1 = As[ty +  8][k] - b;
        float d2 = As[ty + 16][k] - b;
        float d3 = As[ty + 24][k] - b;
        acc0 = fmaf(d0, d0, acc0);
        acc1 = fmaf(d1, d1, acc1);
        acc2 = fmaf(d2, d2, acc2);
        acc3 = fmaf(d3, d3, acc3);
    }
    int jcol = bj + tx;
    g_dist[(size_t)(bi + ty +  0) * n + jcol] = sqrtf(acc0);
    g_dist[(size_t)(bi + ty +  8) * n + jcol] = sqrtf(acc1);
    g_dist[(size_t)(bi + ty + 16) * n + jcol] = sqrtf(acc2);
    g_dist[(size_t)(bi + ty + 24) * n + jcol] = sqrtf(acc3);
}

// ---------------------------------------------------------------------------
// Per-anchor triplet accumulation. One block per anchor i.
// Compact dist row into pos/neg lists (warp-aggregated), then each thread
// caches its <=3 negatives in registers and sweeps the positives.
// ---------------------------------------------------------------------------
__global__ void __launch_bounds__(256) triplet_kernel(int n) {
    __shared__ float pos_d[NMAX];
    __shared__ float neg_d[NMAX];
    __shared__ int sp, sn;
    __shared__ float wsum[8];
    __shared__ int   wcnt[8];

    const int i   = blockIdx.x;
    const int tid = threadIdx.x;
    const int lane = tid & 31;
    const int wid  = tid >> 5;
    const unsigned lmask_lt = (1u << lane) - 1u;

    if (tid == 0) { sp = 0; sn = 0; }
    __syncthreads();

    const int li = g_lab[i];
    const float* __restrict__ drow = &g_dist[(size_t)i * n];

    // Warp-aggregated compaction of row i into pos/neg distance lists.
    for (int base = wid * 32; base < n; base += (blockDim.x >> 5) * 32) {
        int j = base + lane;
        bool inb = (j < n) && (j != i);
        float dv = 0.f;
        int lj = 0;
        if (inb) { dv = drow[j]; lj = g_lab[j]; }
        bool isp = inb && (lj == li);
        bool isn = inb && (lj != li);
        unsigned mp = __ballot_sync(0xFFFFFFFFu, isp);
        unsigned mn = __ballot_sync(0xFFFFFFFFu, isn);
        int bp = 0, bn = 0;
        if (lane == 0) {
            if (mp) bp = atomicAdd(&sp, __popc(mp));
            if (mn) bn = atomicAdd(&sn, __popc(mn));
        }
        bp = __shfl_sync(0xFFFFFFFFu, bp, 0);
        bn = __shfl_sync(0xFFFFFFFFu, bn, 0);
        if (isp) pos_d[bp + __popc(mp & lmask_lt)] = dv;
        if (isn) neg_d[bn + __popc(mn & lmask_lt)] = dv;
    }
    __syncthreads();

    const int P  = sp;
    const int Nn = sn;

    // Register-cache this thread's negatives (Nn <= n-1 <= 1023; 4 regs @256thr).
    const float SENT = 3.0e38f;
    float nk0 = (tid           < Nn) ? neg_d[tid]           : SENT;
    float nk1 = (tid + 256     < Nn) ? neg_d[tid + 256]     : SENT;
    float nk2 = (tid + 512     < Nn) ? neg_d[tid + 512]     : SENT;
    float nk3 = (tid + 768     < Nn) ? neg_d[tid + 768]     : SENT;

    float lsum = 0.f;
    int   lcnt = 0;
    for (int j = 0; j < P; j++) {
        float t0 = pos_d[j] + MARGIN;       // broadcast LDS
        if (nk0 < t0) { lsum += t0 - nk0; lcnt++; }
        if (nk1 < t0) { lsum += t0 - nk1; lcnt++; }
        if (nk2 < t0) { lsum += t0 - nk2; lcnt++; }
        if (nk3 < t0) { lsum += t0 - nk3; lcnt++; }
    }

    // Block reduce.
    #pragma unroll
    for (int off = 16; off; off >>= 1) {
        lsum += __shfl_down_sync(0xFFFFFFFFu, lsum, off);
        lcnt += __shfl_down_sync(0xFFFFFFFFu, lcnt, off);
    }
    if (lane == 0) { wsum[wid] = lsum; wcnt[wid] = lcnt; }
    __syncthreads();
    if (tid == 0) {
        float s = 0.f; int c = 0;
        #pragma unroll
        for (int w = 0; w < 8; w++) { s += wsum[w]; c += wcnt[w]; }
        g_psum[i]   = s;
        g_pcnt[i]   = c;
        g_pvalid[i] = P * Nn;
    }
}

// ---------------------------------------------------------------------------
// Final reduction over anchors -> [loss, num_valid, num_non_easy, frac]
// ---------------------------------------------------------------------------
__global__ void finalize_kernel(float* __restrict__ out, int n) {
    __shared__ float ws[8];
    __shared__ long long wc[8], wv[8];
    const int tid  = threadIdx.x;
    const int lane = tid & 31;
    const int wid  = tid >> 5;

    float s = 0.f;
    long long c = 0, v = 0;
    for (int idx = tid; idx < n; idx += blockDim.x) {
        s += g_psum[idx];
        c += (long long)g_pcnt[idx];
        v += (long long)g_pvalid[idx];
    }
    #pragma unroll
    for (int off = 16; off; off >>= 1) {
        s += __shfl_down_sync(0xFFFFFFFFu, s, off);
        c += __shfl_down_sync(0xFFFFFFFFu, c, off);
        v += __shfl_down_sync(0xFFFFFFFFu, v, off);
    }
    if (lane == 0) { ws[wid] = s; wc[wid] = c; wv[wid] = v; }
    __syncthreads();
    if (tid == 0) {
        float total = 0.f;
        long long cnt = 0, val = 0;
        #pragma unroll
        for (int w = 0; w < 8; w++) { total += ws[w]; cnt += wc[w]; val += wv[w]; }
        float num_non   = (float)cnt;
        float num_valid = (float)val;
        float loss = (cnt > 0) ? total / fmaxf(num_non, 1.0f) : 0.0f;
        float frac = num_non / (num_valid + 1e-16f);
        out[0] = loss;
        out[1] = num_valid;
        out[2] = num_non;
        out[3] = frac;
    }
}

extern "C" void kernel_launch(void* const* d_in, const int* in_sizes, int n_in,
                              void* d_out, int out_size) {
    const float* e   = (const float*)d_in[0];   // embeddings [8,80,128] fp32
    const int*   lab = (const int*)d_in[1];     // labels, int32 or int64 view
    int n = in_sizes[1];                        // 640 (flattened anchors)

    normalize_labels_kernel<<<1, 256>>>(lab, n);
    dim3 grid(n / 32, n / 32);
    dist_kernel<<<grid, 256>>>(e, n);
    triplet_kernel<<<n, 256>>>(n);
    finalize_kernel<<<1, 256>>>((float*)d_out, n);
}